// round 16
// baseline (speedup 1.0000x reference)
#include <cuda_runtime.h>
#include <cuda_bf16.h>

// SpatialAttention, factored: m1m2 = Qt(K Jt)K -> rank-8 bilinear form.
// R14: proj 512-thread (ci split 4-way) + writes out=x for its center lines
//      (memcpy node removed); attn epilogue uses red.global.add.v2.f32.

#define BATCH 2
#define NSP   4096
#define NC    32
#define MSPLIT 8
#define MT    64
#define BLK_ROWS 64          // 4 warps x 16 rows

typedef unsigned long long ull;
typedef unsigned int u32;

// ---- scratch ----
__device__ float g_Q[BATCH * NSP * 8];
__device__ float g_K[BATCH * NSP * 8];
__device__ float g_J[BATCH * NSP * 8];
__device__ __nv_bfloat16 g_Vt[BATCH * NC * NSP];   // [b][c][n] bf16
__device__ float g_M[BATCH * 64];                  // 0.5 * (K Jt)

__device__ __forceinline__ u32 cvt_bf2(float hi, float lo) {
    u32 r; asm("cvt.rn.bf16x2.f32 %0, %1, %2;" : "=r"(r) : "f"(hi), "f"(lo)); return r;
}
__device__ __forceinline__ u32 tanh_bf2(u32 x) {
    u32 r; asm("tanh.approx.bf16x2 %0, %1;" : "=r"(r) : "r"(x)); return r;
}
__device__ __forceinline__ u32 fma_bf2(u32 a, u32 b, u32 c) {
    u32 r; asm("fma.rn.bf16x2 %0, %1, %2, %3;" : "=r"(r) : "r"(a), "r"(b), "r"(c)); return r;
}
__device__ __forceinline__ u32 tf32c(float x) {
    u32 r; asm("cvt.rna.tf32.f32 %0, %1;" : "=r"(r) : "f"(x)); return r;
}
__device__ __forceinline__ void mma_tf32(float* c, const u32* a, u32 b0, u32 b1) {
    asm("mma.sync.aligned.m16n8k8.row.col.f32.tf32.tf32.f32 "
        "{%0,%1,%2,%3}, {%4,%5,%6,%7}, {%8,%9}, {%0,%1,%2,%3};"
        : "+f"(c[0]), "+f"(c[1]), "+f"(c[2]), "+f"(c[3])
        : "r"(a[0]), "r"(a[1]), "r"(a[2]), "r"(a[3]), "r"(b0), "r"(b1));
}
__device__ __forceinline__ void mma16816(float* c, const u32* a, u32 b0, u32 b1) {
    asm("mma.sync.aligned.m16n8k16.row.col.f32.bf16.bf16.f32 "
        "{%0,%1,%2,%3}, {%4,%5,%6,%7}, {%8,%9}, {%0,%1,%2,%3};"
        : "+f"(c[0]), "+f"(c[1]), "+f"(c[2]), "+f"(c[3])
        : "r"(a[0]), "r"(a[1]), "r"(a[2]), "r"(a[3]), "r"(b0), "r"(b1));
}
__device__ __forceinline__ void cp16(void* smem_dst, const void* gsrc) {
    u32 d = (u32)__cvta_generic_to_shared(smem_dst);
    asm volatile("cp.async.ca.shared.global [%0], [%1], 16;" :: "r"(d), "l"(gsrc));
}
__device__ __forceinline__ void redadd2(float* p, float a, float b) {
    asm volatile("red.global.add.v2.f32 [%0], {%1, %2};"
                 :: "l"(p), "f"(a), "f"(b) : "memory");
}
__device__ __forceinline__ float f4e(const float4& v, int e) {
    return e == 0 ? v.x : e == 1 ? v.y : e == 2 ? v.z : v.w;
}

// ============================================================
// 1) Projections — block = 2 adjacent d-lines; 512 threads:
//    (sg 0..3 over ci quarters) x (h) x (oc); both d positions per thread.
//    Also writes out = x for its two center d-lines (init for attn REDG).
// ============================================================
__global__ __launch_bounds__(512) void proj_kernel(
    const float* __restrict__ x, float* __restrict__ out,
    const float* __restrict__ qw, const float* __restrict__ qb,
    const float* __restrict__ qs, const float* __restrict__ qo,
    const float* __restrict__ kw, const float* __restrict__ kb,
    const float* __restrict__ ks, const float* __restrict__ ko,
    const float* __restrict__ jw, const float* __restrict__ jb,
    const float* __restrict__ js, const float* __restrict__ jo,
    const float* __restrict__ vw, const float* __restrict__ vb,
    const float* __restrict__ vs, const float* __restrict__ vo)
{
    int dg = blockIdx.x;          // 0..7 -> d0 = 2*dg
    int w  = blockIdx.y;          // 0..15
    int b  = blockIdx.z;
    int tid = threadIdx.x;
    int d0 = dg * 2;

    __shared__ float s_c[4][18][36];
    __shared__ float s_wm[2][16][36], s_wp[2][16][36];
    __shared__ float s_qw[32][8][4], s_kw[32][8][4], s_jw[32][8][4];
    __shared__ float s_vw[32][8][4];
    __shared__ float s_part[3][128][15];

    const float4 z4 = make_float4(0.f, 0.f, 0.f, 0.f);

    // ---- weights ----
    {
        const float4* q4 = (const float4*)qw;
        const float4* k4 = (const float4*)kw;
        const float4* j4 = (const float4*)jw;
        if (tid < 192) {
            int flat = tid * 4;
            int t = flat >> 8, rem = flat & 255;
            int ci = rem >> 3, oc0 = rem & 7;
            float4 v = q4[tid];
            s_qw[ci][oc0][t] = v.x; s_qw[ci][oc0 + 1][t] = v.y;
            s_qw[ci][oc0 + 2][t] = v.z; s_qw[ci][oc0 + 3][t] = v.w;
            v = k4[tid];
            s_kw[ci][oc0][t] = v.x; s_kw[ci][oc0 + 1][t] = v.y;
            s_kw[ci][oc0 + 2][t] = v.z; s_kw[ci][oc0 + 3][t] = v.w;
            v = j4[tid];
            s_jw[ci][oc0][t] = v.x; s_jw[ci][oc0 + 1][t] = v.y;
            s_jw[ci][oc0 + 2][t] = v.z; s_jw[ci][oc0 + 3][t] = v.w;
        } else if (tid < 448) {
            int i = tid - 192;
            const float4* v4 = (const float4*)vw;
            int flat = i * 4;
            int ci = flat >> 5, co0 = flat & 31;
            float4 v = v4[i];
            s_vw[ci][(co0 + 0) & 7][(co0 + 0) >> 3] = v.x;
            s_vw[ci][(co0 + 1) & 7][(co0 + 1) >> 3] = v.y;
            s_vw[ci][(co0 + 2) & 7][(co0 + 2) >> 3] = v.z;
            s_vw[ci][(co0 + 3) & 7][(co0 + 3) >> 3] = v.w;
        }
    }

    // ---- x staging (+ out = x for center lines) ----
    {
        const float4* X = (const float4*)x;
        float4* O = (float4*)out;
        long bw = (long)b * 16 + w;
        {   // 4 c-lines (d0-1 .. d0+2): one float4 per thread
            int line = tid >> 7, rem = tid & 127;
            int h = rem >> 3, c4 = rem & 7;
            int d = d0 - 1 + line;
            long gidx = ((bw * 16 + d) * 16 + h) * 8 + c4;
            float4 v = (d >= 0 && d <= 15) ? X[gidx] : z4;
            *(float4*)&s_c[line][h + 1][c4 * 4] = v;
            if (line == 1 || line == 2) O[gidx] = v;   // out = x (center lines)
        }
        if (tid < 64) {
            int line = tid >> 4, rr = tid & 15;
            int row = (rr >> 3) ? 17 : 0;
            *(float4*)&s_c[line][row][(rr & 7) * 4] = z4;
        }
        {   // wm / wp for d0, d0+1: one float4 per thread
            int line = tid >> 7, rem = tid & 127;
            int h = rem >> 3, c4 = rem & 7;
            int dd = line >> 1, side = line & 1;
            int wn = w + (side ? 1 : -1);
            float4 v = (wn >= 0 && wn <= 15)
                ? X[((((long)b * 16 + wn) * 16 + (d0 + dd)) * 16 + h) * 8 + c4] : z4;
            if (side) *(float4*)&s_wp[dd][h][c4 * 4] = v;
            else      *(float4*)&s_wm[dd][h][c4 * 4] = v;
        }
    }
    __syncthreads();

    int oc = tid & 7, h = (tid >> 3) & 15, sg = tid >> 7;   // sg 0..3
    float q0 = 0.f, k0 = 0.f, j0 = 0.f;
    float q1 = 0.f, k1 = 0.f, j1 = 0.f;
    float v0[4] = {0.f, 0.f, 0.f, 0.f};
    float v1[4] = {0.f, 0.f, 0.f, 0.f};

    #pragma unroll
    for (int ch = 0; ch < 2; ch++) {
        int ci0 = sg * 8 + ch * 4;
        float4 c0m = *(const float4*)&s_c[0][h + 1][ci0];
        float4 cc0 = *(const float4*)&s_c[1][h + 1][ci0];
        float4 cc1 = *(const float4*)&s_c[2][h + 1][ci0];
        float4 c1p = *(const float4*)&s_c[3][h + 1][ci0];
        float4 hm0 = *(const float4*)&s_c[1][h][ci0];
        float4 hp0 = *(const float4*)&s_c[1][h + 2][ci0];
        float4 hm1 = *(const float4*)&s_c[2][h][ci0];
        float4 hp1 = *(const float4*)&s_c[2][h + 2][ci0];
        float4 wm0 = *(const float4*)&s_wm[0][h][ci0];
        float4 wp0 = *(const float4*)&s_wp[0][h][ci0];
        float4 wm1 = *(const float4*)&s_wm[1][h][ci0];
        float4 wp1 = *(const float4*)&s_wp[1][h][ci0];
        #pragma unroll
        for (int e = 0; e < 4; e++) {
            int ci = ci0 + e;
            float4 qw4 = *(const float4*)&s_qw[ci][oc][0];
            float4 kw4 = *(const float4*)&s_kw[ci][oc][0];
            float4 jw4 = *(const float4*)&s_jw[ci][oc][0];
            float4 vw4 = *(const float4*)&s_vw[ci][oc][0];
            float x0 = f4e(cc0, e), x1 = f4e(cc1, e);
            q0 += f4e(c0m, e) * qw4.x + x0 * qw4.y + x1 * qw4.z;
            q1 += x0 * qw4.x + x1 * qw4.y + f4e(c1p, e) * qw4.z;
            k0 += f4e(wm0, e) * kw4.x + x0 * kw4.y + f4e(wp0, e) * kw4.z;
            k1 += f4e(wm1, e) * kw4.x + x1 * kw4.y + f4e(wp1, e) * kw4.z;
            j0 += f4e(hm0, e) * jw4.x + x0 * jw4.y + f4e(hp0, e) * jw4.z;
            j1 += f4e(hm1, e) * jw4.x + x1 * jw4.y + f4e(hp1, e) * jw4.z;
            v0[0] += x0 * vw4.x;  v1[0] += x1 * vw4.x;
            v0[1] += x0 * vw4.y;  v1[1] += x1 * vw4.y;
            v0[2] += x0 * vw4.z;  v1[2] += x1 * vw4.z;
            v0[3] += x0 * vw4.w;  v1[3] += x1 * vw4.w;
        }
    }

    if (sg) {
        float* p = s_part[sg - 1][tid & 127];
        p[0] = q0; p[1] = k0; p[2] = j0;
        p[3] = v0[0]; p[4] = v0[1]; p[5] = v0[2]; p[6] = v0[3];
        p[7] = q1; p[8] = k1; p[9] = j1;
        p[10] = v1[0]; p[11] = v1[1]; p[12] = v1[2]; p[13] = v1[3];
    }
    __syncthreads();
    if (!sg) {
        #pragma unroll
        for (int s = 0; s < 3; s++) {
            const float* p = s_part[s][tid];
            q0 += p[0]; k0 += p[1]; j0 += p[2];
            v0[0] += p[3]; v0[1] += p[4]; v0[2] += p[5]; v0[3] += p[6];
            q1 += p[7]; k1 += p[8]; j1 += p[9];
            v1[0] += p[10]; v1[1] += p[11]; v1[2] += p[12]; v1[3] += p[13];
        }

        int n0 = w * 256 + d0 * 16 + h;
        int n1 = n0 + 16;
        float qbv = qb[oc], qsv = qs[oc], qov = qo[oc];
        float kbv = kb[oc], ksv = ks[oc], kov = ko[oc];
        float jbv = jb[oc], jsv = js[oc], jov = jo[oc];
        g_Q[b * (NSP * 8) + n0 * 8 + oc] = fmaxf((q0 + qbv) * qsv + qov, 0.f);
        g_Q[b * (NSP * 8) + n1 * 8 + oc] = fmaxf((q1 + qbv) * qsv + qov, 0.f);
        g_K[b * (NSP * 8) + n0 * 8 + oc] = fmaxf((k0 + kbv) * ksv + kov, 0.f);
        g_K[b * (NSP * 8) + n1 * 8 + oc] = fmaxf((k1 + kbv) * ksv + kov, 0.f);
        g_J[b * (NSP * 8) + n0 * 8 + oc] = fmaxf((j0 + jbv) * jsv + jov, 0.f);
        g_J[b * (NSP * 8) + n1 * 8 + oc] = fmaxf((j1 + jbv) * jsv + jov, 0.f);
        #pragma unroll
        for (int p4 = 0; p4 < 4; p4++) {
            int co = oc + 8 * p4;
            float vbv = vb[co], vsv = vs[co], vov = vo[co];
            g_Vt[b * (NSP * NC) + co * NSP + n0] =
                __float2bfloat16(fmaxf((v0[p4] + vbv) * vsv + vov, 0.f));
            g_Vt[b * (NSP * NC) + co * NSP + n1] =
                __float2bfloat16(fmaxf((v1[p4] + vbv) * vsv + vov, 0.f));
        }
    }
}

// ============================================================
// 2) M[a][j] = 0.5 * sum_n K[a][n] * J[j][n]  — float4 + shuffle reduce
// ============================================================
__global__ __launch_bounds__(256) void m_kernel()
{
    int a = blockIdx.x, j = blockIdx.y, b = blockIdx.z;
    const float4* K = (const float4*)(g_K + b * (NSP * 8) + a * NSP);
    const float4* J = (const float4*)(g_J + b * (NSP * 8) + j * NSP);
    float p = 0.f;
    #pragma unroll
    for (int i = 0; i < 4; i++) {
        int idx = i * 256 + threadIdx.x;
        float4 k4 = K[idx], j4 = J[idx];
        p += k4.x * j4.x + k4.y * j4.y + k4.z * j4.z + k4.w * j4.w;
    }
    #pragma unroll
    for (int o = 16; o; o >>= 1) p += __shfl_xor_sync(0xFFFFFFFFu, p, o);
    __shared__ float red[8];
    if ((threadIdx.x & 31) == 0) red[threadIdx.x >> 5] = p;
    __syncthreads();
    if (threadIdx.x == 0) {
        float s = red[0] + red[1] + red[2] + red[3]
                + red[4] + red[5] + red[6] + red[7];
        g_M[b * 64 + a * 8 + j] = 0.5f * s;
    }
}

// ============================================================
// 3) attn: 2-stage cp.async, MSPLIT=8; epilogue = v2 REDG into out
//    (out pre-initialized to x by proj_kernel).
// ============================================================
__global__ __launch_bounds__(128) void attn_kernel(
    const float* __restrict__ gamma, float* __restrict__ out)
{
    const u32 HALF2 = 0x3F003F00u;   // bf16x2 {0.5, 0.5}

    int ms = blockIdx.x, rt = blockIdx.y, b = blockIdx.z;
    int tid = threadIdx.x, wid = tid >> 5, l = tid & 31;
    int lq = l & 3, lr = l >> 2;
    int rowbase = rt * BLK_ROWS;
    int row0 = rowbase + wid * 16 + lr, row1 = row0 + 8;

    __shared__ float sQ[8][64];
    __shared__ float sM[64];
    __shared__ u32 sKt[2][8][72];
    __shared__ __nv_bfloat16 sV[2][32][72];

    const float* Qb = g_Q + b * (NSP * 8);
    const float* Kb = g_K + b * (NSP * 8);
    const __nv_bfloat16* Vtb = g_Vt + b * (NSP * NC);

    if (tid < 64) sM[tid] = g_M[b * 64 + tid];
    {
        int a = tid >> 4, i = (tid & 15) * 4;
        *(float4*)&sQ[a][i] = *(const float4*)(Qb + a * NSP + rowbase + i);
    }

    const int mbeg = ms * (NSP / MSPLIT);
    const int NT = (NSP / MSPLIT) / MT;   // 8

    int kj = tid >> 4, kmg = (tid & 15) * 4;
    int vc0 = tid >> 3, vmg0 = (tid & 7) * 8;
    int vc1 = (tid + 128) >> 3, vmg1 = vmg0;

    cp16(&sKt[0][kj][kmg], Kb + kj * NSP + mbeg + kmg);
    cp16(&sV[0][vc0][vmg0], Vtb + vc0 * NSP + mbeg + vmg0);
    cp16(&sV[0][vc1][vmg1], Vtb + vc1 * NSP + mbeg + vmg1);
    asm volatile("cp.async.commit_group;");

    __syncthreads();

    float r00 = 0.f, r01 = 0.f, r10 = 0.f, r11 = 0.f;
    int i0 = wid * 16 + lr, i1 = i0 + 8;
    #pragma unroll
    for (int a = 0; a < 8; a++) {
        float q0 = sQ[a][i0], q1 = sQ[a][i1];
        r00 += q0 * sM[a * 8 + lq];
        r01 += q0 * sM[a * 8 + lq + 4];
        r10 += q1 * sM[a * 8 + lq];
        r11 += q1 * sM[a * 8 + lq + 4];
    }
    u32 A32[4] = { tf32c(r00), tf32c(r10), tf32c(r01), tf32c(r11) };

    float acc[16];
    #pragma unroll
    for (int i = 0; i < 16; i++) acc[i] = 0.f;

    for (int ti = 0; ti < NT; ti++) {
        int cur = ti & 1, nxt = cur ^ 1;
        __syncthreads();
        if (ti + 1 < NT) {
            int mb = mbeg + (ti + 1) * MT;
            cp16(&sKt[nxt][kj][kmg], Kb + kj * NSP + mb + kmg);
            cp16(&sV[nxt][vc0][vmg0], Vtb + vc0 * NSP + mb + vmg0);
            cp16(&sV[nxt][vc1][vmg1], Vtb + vc1 * NSP + mb + vmg1);
        }
        asm volatile("cp.async.commit_group;");
        asm volatile("cp.async.wait_group 1;");
        __syncthreads();

        #pragma unroll
        for (int ch = 0; ch < 4; ch++) {
            int cb = ch * 16;
            u32 kb0a = sKt[cur][lq][cb + lr],     kb1a = sKt[cur][lq + 4][cb + lr];
            u32 kb0b = sKt[cur][lq][cb + 8 + lr], kb1b = sKt[cur][lq + 4][cb + 8 + lr];
            float t[8];
            #pragma unroll
            for (int i = 0; i < 8; i++) t[i] = 0.f;
            mma_tf32(t,     A32, kb0a, kb1a);
            mma_tf32(t + 4, A32, kb0b, kb1b);

            u32 Abf[4];
            Abf[0] = fma_bf2(tanh_bf2(cvt_bf2(t[1], t[0])), HALF2, HALF2);
            Abf[1] = fma_bf2(tanh_bf2(cvt_bf2(t[3], t[2])), HALF2, HALF2);
            Abf[2] = fma_bf2(tanh_bf2(cvt_bf2(t[5], t[4])), HALF2, HALF2);
            Abf[3] = fma_bf2(tanh_bf2(cvt_bf2(t[7], t[6])), HALF2, HALF2);

            int m0 = cb + 2 * lq;
            #pragma unroll
            for (int g = 0; g < 4; g++) {
                int c = g * 8 + lr;
                u32 vb0 = *(const u32*)&sV[cur][c][m0];
                u32 vb1 = *(const u32*)&sV[cur][c][m0 + 8];
                mma16816(acc + g * 4, Abf, vb0, vb1);
            }
        }
    }

    // epilogue: out += gamma * acc  (v2 reduction atomics; out = x from proj)
    float gm = gamma[0];
    float* Ob = out + (size_t)b * NSP * NC;
    #pragma unroll
    for (int g = 0; g < 4; g++) {
        int col = g * 8 + lq * 2;
        redadd2(Ob + row0 * NC + col, gm * acc[g * 4 + 0], gm * acc[g * 4 + 1]);
        redadd2(Ob + row1 * NC + col, gm * acc[g * 4 + 2], gm * acc[g * 4 + 3]);
    }
}

// ============================================================
extern "C" void kernel_launch(void* const* d_in, const int* in_sizes, int n_in,
                              void* d_out, int out_size)
{
    const float* x     = (const float*)d_in[0];
    const float* gamma = (const float*)d_in[1];
    const float* qw = (const float*)d_in[2];
    const float* qb = (const float*)d_in[3];
    const float* qs = (const float*)d_in[4];
    const float* qo = (const float*)d_in[5];
    const float* kw = (const float*)d_in[6];
    const float* kb = (const float*)d_in[7];
    const float* ks = (const float*)d_in[8];
    const float* ko = (const float*)d_in[9];
    const float* jw = (const float*)d_in[10];
    const float* jb = (const float*)d_in[11];
    const float* js = (const float*)d_in[12];
    const float* jo = (const float*)d_in[13];
    const float* vw = (const float*)d_in[14];
    const float* vb = (const float*)d_in[15];
    const float* vs = (const float*)d_in[16];
    const float* vo = (const float*)d_in[17];
    float* out = (float*)d_out;

    proj_kernel<<<dim3(8, 16, BATCH), 512>>>(x, out, qw, qb, qs, qo,
                                             kw, kb, ks, ko,
                                             jw, jb, js, jo,
                                             vw, vb, vs, vo);
    m_kernel<<<dim3(8, 8, BATCH), 256>>>();
    attn_kernel<<<dim3(MSPLIT, NSP / BLK_ROWS, BATCH), 128>>>(gamma, out);
}